// round 1
// baseline (speedup 1.0000x reference)
#include <cuda_runtime.h>
#include <math.h>

#define B_  8
#define S_  2048
#define D_  512
#define H_  8
#define DH_ 64
#define M_  (B_*S_)

// Scratch (allocation-free): Q/K/V in [B,H,S,Dh], attn out in [B,S,D]
__device__ float g_q[B_*H_*S_*DH_];
__device__ float g_k[B_*H_*S_*DH_];
__device__ float g_v[B_*H_*S_*DH_];
__device__ float g_attn[M_*D_];

// ---------------------------------------------------------------------------
// SGEMM: C[M=16384, N=512] = A[M,512] @ W[512,512] + bias
// mode 0/1/2: A=x, scatter output into g_q/g_k/g_v as [B,H,S,Dh]
// mode 3:     A=g_attn, plain write to Cout ([B,S,D])
// 128x128 tile, BK=8, 256 threads, 8x8 per thread.
// ---------------------------------------------------------------------------
__global__ void __launch_bounds__(256) gemm_kernel(
    const float* __restrict__ A_in, const float* __restrict__ W,
    const float* __restrict__ bias, float* __restrict__ Cout, int mode)
{
    const int N = D_, K = D_;
    const float* A = (mode == 3) ? (const float*)g_attn : A_in;

    __shared__ float As[8][128];
    __shared__ float Bs[8][128];

    const int tid = threadIdx.x;
    const int tx = tid & 15;          // 0..15 -> col group
    const int ty = tid >> 4;          // 0..15 -> row group
    const int row0 = blockIdx.y * 128;
    const int col0 = blockIdx.x * 128;

    float acc[8][8];
    #pragma unroll
    for (int i = 0; i < 8; i++)
        #pragma unroll
        for (int j = 0; j < 8; j++) acc[i][j] = 0.f;

    const int a_row = tid >> 1;             // 0..127
    const int a_col = (tid & 1) * 4;        // 0 or 4
    const int b_row = tid >> 5;             // 0..7
    const int b_col = (tid & 31) * 4;       // 0..124
    const float* Ap = A + (size_t)(row0 + a_row) * K + a_col;
    const float* Wp = W + (size_t)b_row * N + col0 + b_col;

    for (int k0 = 0; k0 < K; k0 += 8) {
        float4 av = *(const float4*)(Ap + k0);
        float4 bv = *(const float4*)(Wp + (size_t)k0 * N);
        As[a_col + 0][a_row] = av.x;
        As[a_col + 1][a_row] = av.y;
        As[a_col + 2][a_row] = av.z;
        As[a_col + 3][a_row] = av.w;
        *(float4*)&Bs[b_row][b_col] = bv;
        __syncthreads();

        #pragma unroll
        for (int k = 0; k < 8; k++) {
            float ra[8], rb[8];
            *(float4*)(ra)     = *(const float4*)&As[k][ty * 8];
            *(float4*)(ra + 4) = *(const float4*)&As[k][ty * 8 + 4];
            *(float4*)(rb)     = *(const float4*)&Bs[k][tx * 8];
            *(float4*)(rb + 4) = *(const float4*)&Bs[k][tx * 8 + 4];
            #pragma unroll
            for (int i = 0; i < 8; i++)
                #pragma unroll
                for (int j = 0; j < 8; j++)
                    acc[i][j] += ra[i] * rb[j];
        }
        __syncthreads();
    }

    const int c0 = col0 + tx * 8;
    if (mode == 3) {
        #pragma unroll
        for (int i = 0; i < 8; i++) {
            int r = row0 + ty * 8 + i;
            float* dst = Cout + (size_t)r * N + c0;
            #pragma unroll
            for (int j = 0; j < 8; j++) dst[j] = acc[i][j] + bias[c0 + j];
        }
    } else {
        float* Qd = (mode == 0) ? g_q : (mode == 1) ? g_k : g_v;
        const int h   = c0 >> 6;       // 8 consecutive cols stay in one head
        const int dh0 = c0 & 63;
        #pragma unroll
        for (int i = 0; i < 8; i++) {
            int r = row0 + ty * 8 + i;
            int b = r >> 11, s = r & 2047;
            float* dst = Qd + ((size_t)(b * H_ + h) * S_ + s) * DH_ + dh0;
            #pragma unroll
            for (int j = 0; j < 8; j++) dst[j] = acc[i][j] + bias[c0 + j];
        }
    }
}

// ---------------------------------------------------------------------------
// Flash attention with periodic-prior bias.
// bias[i][j] = log1p(2 + exp(-2*(|i-j| mod 30)^2))   (30-entry table)
// One thread per query row (BM=128 rows/CTA); K/V tiles (BN=32 x 64) in SMEM,
// broadcast reads; Q and O accumulator in registers; online softmax.
// grid = (S/128, B*H)
// ---------------------------------------------------------------------------
__global__ void __launch_bounds__(128) attn_kernel()
{
    const int bh  = blockIdx.y;           // 0..63
    const int tid = threadIdx.x;          // 0..127
    const int row = blockIdx.x * 128 + tid;

    __shared__ float Ks[32][64];
    __shared__ float Vs[32][64];
    __shared__ float btab[30];
    if (tid < 30)
        btab[tid] = log1pf(2.f + expf(-2.f * (float)(tid * tid)));

    // Q row in registers, pre-scaled by 1/sqrt(Dh)=0.125
    const float* qrow = g_q + ((size_t)bh * S_ + row) * DH_;
    float q[64];
    #pragma unroll
    for (int i = 0; i < 16; i++) {
        float4 t = *(const float4*)(qrow + 4 * i);
        q[4*i+0] = t.x * 0.125f;
        q[4*i+1] = t.y * 0.125f;
        q[4*i+2] = t.z * 0.125f;
        q[4*i+3] = t.w * 0.125f;
    }

    float o[64];
    #pragma unroll
    for (int i = 0; i < 64; i++) o[i] = 0.f;
    float mprev = -1e30f, lsum = 0.f;

    const float* Kb = g_k + (size_t)bh * S_ * DH_;
    const float* Vb = g_v + (size_t)bh * S_ * DH_;
    const int lr = tid >> 2;            // 0..31 tile row
    const int lc = (tid & 3) * 16;      // 0/16/32/48

    for (int j0 = 0; j0 < S_; j0 += 32) {
        __syncthreads();
        {
            const float4* ks = (const float4*)(Kb + (size_t)(j0 + lr) * DH_ + lc);
            const float4* vs = (const float4*)(Vb + (size_t)(j0 + lr) * DH_ + lc);
            float4* kd = (float4*)&Ks[lr][lc];
            float4* vd = (float4*)&Vs[lr][lc];
            #pragma unroll
            for (int i = 0; i < 4; i++) { kd[i] = ks[i]; vd[i] = vs[i]; }
        }
        __syncthreads();

        float s[32];
        #pragma unroll 4
        for (int j = 0; j < 32; j++) {
            float a = 0.f;
            #pragma unroll
            for (int k = 0; k < 64; k++) a += q[k] * Ks[j][k];
            int d = row - (j0 + j); if (d < 0) d = -d;
            s[j] = a + btab[d % 30];
        }

        float tmax = mprev;
        #pragma unroll
        for (int j = 0; j < 32; j++) tmax = fmaxf(tmax, s[j]);
        float alpha = __expf(mprev - tmax);
        mprev = tmax;
        lsum *= alpha;
        #pragma unroll
        for (int k = 0; k < 64; k++) o[k] *= alpha;

        #pragma unroll 4
        for (int j = 0; j < 32; j++) {
            float p = __expf(s[j] - tmax);
            lsum += p;
            #pragma unroll
            for (int k = 0; k < 64; k++) o[k] += p * Vs[j][k];
        }
    }

    const float inv = 1.f / lsum;
    const int b = bh >> 3, h = bh & 7;
    float* dst = g_attn + ((size_t)(b * S_ + row)) * D_ + h * DH_;
    #pragma unroll
    for (int i = 0; i < 16; i++) {
        float4 t = { o[4*i+0]*inv, o[4*i+1]*inv, o[4*i+2]*inv, o[4*i+3]*inv };
        *(float4*)(dst + 4 * i) = t;
    }
}

// ---------------------------------------------------------------------------
extern "C" void kernel_launch(void* const* d_in, const int* in_sizes, int n_in,
                              void* d_out, int out_size)
{
    const float* x  = (const float*)d_in[0];
    const float* Wq = (const float*)d_in[1];
    const float* bq = (const float*)d_in[2];
    const float* Wk = (const float*)d_in[3];
    const float* bk = (const float*)d_in[4];
    const float* Wv = (const float*)d_in[5];
    const float* bv = (const float*)d_in[6];
    const float* Wo = (const float*)d_in[7];
    const float* bo = (const float*)d_in[8];
    float* out = (float*)d_out;

    dim3 ggrid(D_ / 128, M_ / 128);   // (4, 128)
    gemm_kernel<<<ggrid, 256>>>(x, Wq, bq, nullptr, 0);
    gemm_kernel<<<ggrid, 256>>>(x, Wk, bk, nullptr, 1);
    gemm_kernel<<<ggrid, 256>>>(x, Wv, bv, nullptr, 2);
    attn_kernel<<<dim3(S_ / 128, B_ * H_), 128>>>();
    gemm_kernel<<<ggrid, 256>>>(nullptr, Wo, bo, out, 3);
}

// round 3
// speedup vs baseline: 3.0491x; 3.0491x over previous
#include <cuda_runtime.h>
#include <cuda_fp16.h>
#include <cstdint>
#include <math.h>

#define B_  8
#define S_  2048
#define D_  512
#define H_  8
#define DH_ 64
#define M_  (B_*S_)

// ---------------- scratch (allocation-free) ----------------
__device__ __half g_xhi[M_*D_], g_xlo[M_*D_];
__device__ __half g_whi[4*D_*D_], g_wlo[4*D_*D_];
__device__ __half g_qhi[M_*D_], g_qlo[M_*D_];   // [bh][s][64]
__device__ __half g_khi[M_*D_], g_klo[M_*D_];
__device__ __half g_vhi[M_*D_], g_vlo[M_*D_];
__device__ __half g_ohi[M_*D_], g_olo[M_*D_];   // [16384][512]

// ---------------- helpers ----------------
__device__ __forceinline__ uint32_t smem_u32(const void* p) {
    uint32_t a;
    asm("{ .reg .u64 t; cvta.to.shared.u64 t, %1; cvt.u32.u64 %0, t; }" : "=r"(a) : "l"(p));
    return a;
}
__device__ __forceinline__ void ldsm4(uint32_t* r, uint32_t a) {
    asm volatile("ldmatrix.sync.aligned.m8n8.x4.shared.b16 {%0,%1,%2,%3}, [%4];"
                 : "=r"(r[0]), "=r"(r[1]), "=r"(r[2]), "=r"(r[3]) : "r"(a));
}
__device__ __forceinline__ void ldsm4t(uint32_t* r, uint32_t a) {
    asm volatile("ldmatrix.sync.aligned.m8n8.x4.trans.shared.b16 {%0,%1,%2,%3}, [%4];"
                 : "=r"(r[0]), "=r"(r[1]), "=r"(r[2]), "=r"(r[3]) : "r"(a));
}
__device__ __forceinline__ void mma_f16(float* d, const uint32_t* a, uint32_t b0, uint32_t b1) {
    asm volatile(
        "mma.sync.aligned.m16n8k16.row.col.f32.f16.f16.f32 "
        "{%0,%1,%2,%3}, {%4,%5,%6,%7}, {%8,%9}, {%0,%1,%2,%3};"
        : "+f"(d[0]), "+f"(d[1]), "+f"(d[2]), "+f"(d[3])
        : "r"(a[0]), "r"(a[1]), "r"(a[2]), "r"(a[3]), "r"(b0), "r"(b1));
}
#define MOD30(d) ((d) - (((d) * 2185) >> 16) * 30)   // exact for 0 <= d < 2048

// ---------------- split kernels ----------------
__global__ void split_x_kernel(const float* __restrict__ x) {
    int i = blockIdx.x * 256 + threadIdx.x;
    float v = x[i];
    __half h = __float2half_rn(v);
    g_xhi[i] = h;
    g_xlo[i] = __float2half_rn(v - __half2float(h));
}
__global__ void split_w_kernel(const float* __restrict__ Wq, const float* __restrict__ Wk,
                               const float* __restrict__ Wv, const float* __restrict__ Wo) {
    int z = blockIdx.y;
    const float* W = (z == 0) ? Wq : (z == 1) ? Wk : (z == 2) ? Wv : Wo;
    int i = blockIdx.x * 256 + threadIdx.x;
    float v = W[i];
    __half h = __float2half_rn(v);
    g_whi[z * D_ * D_ + i] = h;
    g_wlo[z * D_ * D_ + i] = __float2half_rn(v - __half2float(h));
}

// ---------------------------------------------------------------------------
// GEMM: C[16384,512] = A[16384,512] @ W[512,512] + bias   (split-fp16 mma.sync)
// mode 0/1/2: A = x, write hi/lo halves into q/k/v [bh][s][64] (Q scaled 0.125)
// mode 3:     A = o,  write fp32 to Cout
// ---------------------------------------------------------------------------
__global__ void __launch_bounds__(256) gemm_fp16(int mode, const float* __restrict__ bias,
                                                 float* __restrict__ Cout)
{
    const __half* Ahi = (mode == 3) ? g_ohi : g_xhi;
    const __half* Alo = (mode == 3) ? g_olo : g_xlo;
    const __half* Bhi = g_whi + (size_t)mode * D_ * D_;
    const __half* Blo = g_wlo + (size_t)mode * D_ * D_;

    __shared__ __half sA[2][128 * 40];   // [split][row 128][k 32 + pad 8]
    __shared__ __half sB[2][32 * 136];   // [split][k 32][n 128 + pad 8]

    const int tid = threadIdx.x, lane = tid & 31, wid = tid >> 5;
    const int wm = wid >> 1, wn = wid & 1;              // 4 x 2 warp grid
    const int row0 = blockIdx.y * 128, col0 = blockIdx.x * 128;

    float acc[2][8][4];
    #pragma unroll
    for (int mt = 0; mt < 2; mt++)
        #pragma unroll
        for (int nt = 0; nt < 8; nt++)
            #pragma unroll
            for (int e = 0; e < 4; e++) acc[mt][nt][e] = 0.f;

    for (int c = 0; c < 16; c++) {
        #pragma unroll
        for (int i = 0; i < 4; i++) {
            int idx = tid + 256 * i;                     // 0..1023
            {   // A: 2 splits x 128 rows x 4 float4
                int spl = idx >> 9, rr = (idx >> 2) & 127, cc = (idx & 3) * 8;
                const __half* src = (spl ? Alo : Ahi) + (size_t)(row0 + rr) * D_ + c * 32 + cc;
                *(float4*)&sA[spl][rr * 40 + cc] = *(const float4*)src;
            }
            {   // B: 2 splits x 32 rows x 16 float4
                int spl = idx >> 9, rr = (idx >> 4) & 31, cc = (idx & 15) * 8;
                const __half* src = (spl ? Blo : Bhi) + (size_t)(c * 32 + rr) * D_ + col0 + cc;
                *(float4*)&sB[spl][rr * 136 + cc] = *(const float4*)src;
            }
        }
        __syncthreads();

        #pragma unroll
        for (int kt = 0; kt < 2; kt++) {
            uint32_t Ah[2][4], Al[2][4], Bh[8][2], Bl[8][2];
            #pragma unroll
            for (int mt = 0; mt < 2; mt++) {
                int rr = 32 * wm + 16 * mt + (lane & 15);
                int kk = 16 * kt + (lane >> 4) * 8;
                ldsm4(Ah[mt], smem_u32(&sA[0][rr * 40 + kk]));
                ldsm4(Al[mt], smem_u32(&sA[1][rr * 40 + kk]));
            }
            #pragma unroll
            for (int ng = 0; ng < 4; ng++) {
                int kr = 16 * kt + (lane & 15);
                int cc = 64 * wn + 16 * ng + (lane >> 4) * 8;
                uint32_t t4[4];
                ldsm4t(t4, smem_u32(&sB[0][kr * 136 + cc]));
                Bh[2*ng][0] = t4[0]; Bh[2*ng][1] = t4[1];
                Bh[2*ng+1][0] = t4[2]; Bh[2*ng+1][1] = t4[3];
                ldsm4t(t4, smem_u32(&sB[1][kr * 136 + cc]));
                Bl[2*ng][0] = t4[0]; Bl[2*ng][1] = t4[1];
                Bl[2*ng+1][0] = t4[2]; Bl[2*ng+1][1] = t4[3];
            }
            #pragma unroll
            for (int mt = 0; mt < 2; mt++)
                #pragma unroll
                for (int nt = 0; nt < 8; nt++) {
                    mma_f16(acc[mt][nt], Ah[mt], Bh[nt][0], Bh[nt][1]);
                    mma_f16(acc[mt][nt], Al[mt], Bh[nt][0], Bh[nt][1]);
                    mma_f16(acc[mt][nt], Ah[mt], Bl[nt][0], Bl[nt][1]);
                }
        }
        __syncthreads();
    }

    // epilogue
    const float sc = (mode == 0) ? 0.125f : 1.f;
    __half* Dhi = (mode == 0) ? g_qhi : (mode == 1) ? g_khi : g_vhi;
    __half* Dlo = (mode == 0) ? g_qlo : (mode == 1) ? g_klo : g_vlo;
    #pragma unroll
    for (int mt = 0; mt < 2; mt++)
        #pragma unroll
        for (int nt = 0; nt < 8; nt++) {
            int row = row0 + 32 * wm + 16 * mt + (lane >> 2);
            int col = col0 + 64 * wn + 8 * nt + 2 * (lane & 3);
            float b0 = bias[col], b1 = bias[col + 1];
            float c0 = acc[mt][nt][0] + b0, c1 = acc[mt][nt][1] + b1;
            float c2 = acc[mt][nt][2] + b0, c3 = acc[mt][nt][3] + b1;
            if (mode == 3) {
                *(float2*)&Cout[(size_t)row * D_ + col] = make_float2(c0, c1);
                *(float2*)&Cout[(size_t)(row + 8) * D_ + col] = make_float2(c2, c3);
            } else {
                c0 *= sc; c1 *= sc; c2 *= sc; c3 *= sc;
                int h = col >> 6, dh = col & 63;
                int b = row >> 11, s = row & 2047;
                size_t i0 = ((size_t)(b * H_ + h) * S_ + s) * DH_ + dh;
                half2 h01 = __floats2half2_rn(c0, c1);
                *(half2*)&Dhi[i0] = h01;
                *(half2*)&Dlo[i0] = __floats2half2_rn(c0 - __low2float(h01), c1 - __high2float(h01));
                half2 h23 = __floats2half2_rn(c2, c3);
                *(half2*)&Dhi[i0 + 8 * DH_] = h23;
                *(half2*)&Dlo[i0 + 8 * DH_] = __floats2half2_rn(c2 - __low2float(h23), c3 - __high2float(h23));
            }
        }
}

// ---------------------------------------------------------------------------
// Flash attention, split-fp16 mma.sync. Warp = 16 query rows; key tiles of 64.
// bias[i][j] = log1p(2 + exp(-2*(|i-j| mod 30)^2)), 30-entry table.
// grid = (16, 64), 256 threads.
// ---------------------------------------------------------------------------
__global__ void __launch_bounds__(256) attn_fp16()
{
    const int bh = blockIdx.y, tid = threadIdx.x, lane = tid & 31, w = tid >> 5;
    const int q0 = blockIdx.x * 128;

    __shared__ __half sK[2][64 * 72];   // [hi/lo][row 64][dh 64 + pad 8]
    __shared__ __half sV[2][64 * 72];
    __shared__ float btab[32];
    if (tid < 30) btab[tid] = log1pf(2.f + __expf(-2.f * (float)(tid * tid)));

    const size_t base = (size_t)bh * S_ * DH_;

    // stage Q (hi rows 0-127 -> sK[0],sK[1]; lo -> sV[0],sV[1]) and ldmatrix frags
    #pragma unroll
    for (int i = 0; i < 8; i++) {
        int idx = tid + 256 * i;             // 0..2047
        int spl = idx >> 10;
        int rr = (idx >> 3) & 127, cc = (idx & 7) * 8;
        const __half* src = (spl ? g_qlo : g_qhi) + base + (size_t)(q0 + rr) * DH_ + cc;
        __half* dst = (spl ? sV[rr >> 6] : sK[rr >> 6]) + (rr & 63) * 72 + cc;
        *(float4*)dst = *(const float4*)src;
    }
    __syncthreads();
    uint32_t Qh[4][4], Ql[4][4];
    {
        int buf = (w >= 4);
        int srow = (16 * w) & 63;
        #pragma unroll
        for (int kt = 0; kt < 4; kt++) {
            int r = srow + (lane & 15), k = 16 * kt + (lane >> 4) * 8;
            ldsm4(Qh[kt], smem_u32(&sK[buf][r * 72 + k]));
            ldsm4(Ql[kt], smem_u32(&sV[buf][r * 72 + k]));
        }
    }

    float O[8][4];
    #pragma unroll
    for (int nt = 0; nt < 8; nt++)
        #pragma unroll
        for (int e = 0; e < 4; e++) O[nt][e] = 0.f;
    float m0 = -1e30f, m1 = -1e30f, l0 = 0.f, l1 = 0.f;
    const int row_a = q0 + 16 * w + (lane >> 2);     // global s of first row

    for (int j0 = 0; j0 < S_; j0 += 64) {
        __syncthreads();
        #pragma unroll
        for (int i = 0; i < 8; i++) {
            int idx = tid + 256 * i;                 // 4 arrays x 512 float4
            int arr = idx >> 9;
            int rr = (idx >> 3) & 63, cc = (idx & 7) * 8;
            const __half* src = (arr == 0 ? g_khi : arr == 1 ? g_klo : arr == 2 ? g_vhi : g_vlo)
                                + base + (size_t)(j0 + rr) * DH_ + cc;
            __half* dst = (arr < 2 ? sK[arr & 1] : sV[arr & 1]) + rr * 72 + cc;
            *(float4*)dst = *(const float4*)src;
        }
        __syncthreads();

        // ---- S = Q K^T (3-term split) ----
        float Sc[8][4];
        #pragma unroll
        for (int nt = 0; nt < 8; nt++)
            #pragma unroll
            for (int e = 0; e < 4; e++) Sc[nt][e] = 0.f;

        #pragma unroll
        for (int kt = 0; kt < 4; kt++) {
            uint32_t Kh[8][2], Kl[8][2];
            #pragma unroll
            for (int kq = 0; kq < 4; kq++) {
                int kr = 16 * kq + (lane & 15), kk = 16 * kt + (lane >> 4) * 8;
                uint32_t t4[4];
                ldsm4(t4, smem_u32(&sK[0][kr * 72 + kk]));
                Kh[2*kq][0] = t4[0]; Kh[2*kq][1] = t4[2];
                Kh[2*kq+1][0] = t4[1]; Kh[2*kq+1][1] = t4[3];
                ldsm4(t4, smem_u32(&sK[1][kr * 72 + kk]));
                Kl[2*kq][0] = t4[0]; Kl[2*kq][1] = t4[2];
                Kl[2*kq+1][0] = t4[1]; Kl[2*kq+1][1] = t4[3];
            }
            #pragma unroll
            for (int nt = 0; nt < 8; nt++) {
                mma_f16(Sc[nt], Qh[kt], Kh[nt][0], Kh[nt][1]);
                mma_f16(Sc[nt], Ql[kt], Kh[nt][0], Kh[nt][1]);
                mma_f16(Sc[nt], Qh[kt], Kl[nt][0], Kl[nt][1]);
            }
        }

        // ---- bias + online softmax ----
        #pragma unroll
        for (int nt = 0; nt < 8; nt++) {
            int colb = j0 + 8 * nt + 2 * (lane & 3);
            #pragma unroll
            for (int e = 0; e < 2; e++) {
                int da = row_a - (colb + e); da = da < 0 ? -da : da;
                int db = row_a + 8 - (colb + e); db = db < 0 ? -db : db;
                Sc[nt][e]     += btab[MOD30(da)];
                Sc[nt][2 + e] += btab[MOD30(db)];
            }
        }
        float ma = m0, mb = m1;
        #pragma unroll
        for (int nt = 0; nt < 8; nt++) {
            ma = fmaxf(ma, fmaxf(Sc[nt][0], Sc[nt][1]));
            mb = fmaxf(mb, fmaxf(Sc[nt][2], Sc[nt][3]));
        }
        ma = fmaxf(ma, __shfl_xor_sync(0xFFFFFFFF, ma, 1));
        ma = fmaxf(ma, __shfl_xor_sync(0xFFFFFFFF, ma, 2));
        mb = fmaxf(mb, __shfl_xor_sync(0xFFFFFFFF, mb, 1));
        mb = fmaxf(mb, __shfl_xor_sync(0xFFFFFFFF, mb, 2));
        float aa = __expf(m0 - ma), ab = __expf(m1 - mb);
        m0 = ma; m1 = mb;
        float suma = 0.f, sumb = 0.f;
        #pragma unroll
        for (int nt = 0; nt < 8; nt++) {
            Sc[nt][0] = __expf(Sc[nt][0] - ma); suma += Sc[nt][0];
            Sc[nt][1] = __expf(Sc[nt][1] - ma); suma += Sc[nt][1];
            Sc[nt][2] = __expf(Sc[nt][2] - mb); sumb += Sc[nt][2];
            Sc[nt][3] = __expf(Sc[nt][3] - mb); sumb += Sc[nt][3];
        }
        suma += __shfl_xor_sync(0xFFFFFFFF, suma, 1);
        suma += __shfl_xor_sync(0xFFFFFFFF, suma, 2);
        sumb += __shfl_xor_sync(0xFFFFFFFF, sumb, 1);
        sumb += __shfl_xor_sync(0xFFFFFFFF, sumb, 2);
        l0 = l0 * aa + suma;
        l1 = l1 * ab + sumb;
        #pragma unroll
        for (int nt = 0; nt < 8; nt++) {
            O[nt][0] *= aa; O[nt][1] *= aa; O[nt][2] *= ab; O[nt][3] *= ab;
        }

        // ---- O += P V (3-term split) ----
        #pragma unroll
        for (int kg = 0; kg < 4; kg++) {
            uint32_t Ph[4], Pl[4];
            #pragma unroll
            for (int half_idx = 0; half_idx < 2; half_idx++) {
                int nt = 2 * kg + half_idx;
                half2 ha = __floats2half2_rn(Sc[nt][0], Sc[nt][1]);
                half2 hb = __floats2half2_rn(Sc[nt][2], Sc[nt][3]);
                Ph[2 * half_idx]     = *(uint32_t*)&ha;
                Ph[2 * half_idx + 1] = *(uint32_t*)&hb;
                half2 la = __floats2half2_rn(Sc[nt][0] - __low2float(ha),
                                             Sc[nt][1] - __high2float(ha));
                half2 lb = __floats2half2_rn(Sc[nt][2] - __low2float(hb),
                                             Sc[nt][3] - __high2float(hb));
                Pl[2 * half_idx]     = *(uint32_t*)&la;
                Pl[2 * half_idx + 1] = *(uint32_t*)&lb;
            }
            #pragma unroll
            for (int vg = 0; vg < 4; vg++) {
                int kr = 16 * kg + (lane & 15), dd = 16 * vg + (lane >> 4) * 8;
                uint32_t t4[4], u4[4];
                ldsm4t(t4, smem_u32(&sV[0][kr * 72 + dd]));
                ldsm4t(u4, smem_u32(&sV[1][kr * 72 + dd]));
                mma_f16(O[2*vg],   Ph, t4[0], t4[1]);
                mma_f16(O[2*vg],   Pl, t4[0], t4[1]);
                mma_f16(O[2*vg],   Ph, u4[0], u4[1]);
                mma_f16(O[2*vg+1], Ph, t4[2], t4[3]);
                mma_f16(O[2*vg+1], Pl, t4[2], t4[3]);
                mma_f16(O[2*vg+1], Ph, u4[2], u4[3]);
            }
        }
    }

    // ---- epilogue: normalize, split, store to o [16384,512] ----
    const float inva = 1.f / l0, invb = 1.f / l1;
    const int b = bh >> 3, h = bh & 7;
    #pragma unroll
    for (int nt = 0; nt < 8; nt++) {
        int dh = 8 * nt + 2 * (lane & 3);
        float c0 = O[nt][0] * inva, c1 = O[nt][1] * inva;
        float c2 = O[nt][2] * invb, c3 = O[nt][3] * invb;
        size_t ra = ((size_t)(b * S_ + row_a)) * D_ + h * DH_ + dh;
        size_t rb = ra + 8 * D_;
        half2 h01 = __floats2half2_rn(c0, c1);
        *(half2*)&g_ohi[ra] = h01;
        *(half2*)&g_olo[ra] = __floats2half2_rn(c0 - __low2float(h01), c1 - __high2float(h01));
        half2 h23 = __floats2half2_rn(c2, c3);
        *(half2*)&g_ohi[rb] = h23;
        *(half2*)&g_olo[rb] = __floats2half2_rn(c2 - __low2float(h23), c3 - __high2float(h23));
    }
}

// ---------------------------------------------------------------------------
extern "C" void kernel_launch(void* const* d_in, const int* in_sizes, int n_in,
                              void* d_out, int out_size)
{
    const float* x  = (const float*)d_in[0];
    const float* Wq = (const float*)d_in[1];
    const float* bq = (const float*)d_in[2];
    const float* Wk = (const float*)d_in[3];
    const float* bk = (const float*)d_in[4];
    const float* Wv = (const float*)d_in[5];
    const float* bv = (const float*)d_in[6];
    const float* Wo = (const float*)d_in[7];
    const float* bo = (const float*)d_in[8];
    float* out = (float*)d_out;

    split_x_kernel<<<M_ * D_ / 256, 256>>>(x);
    split_w_kernel<<<dim3(D_ * D_ / 256, 4), 256>>>(Wq, Wk, Wv, Wo);

    dim3 ggrid(4, 128);
    gemm_fp16<<<ggrid, 256>>>(0, bq, nullptr);
    gemm_fp16<<<ggrid, 256>>>(1, bk, nullptr);
    gemm_fp16<<<ggrid, 256>>>(2, bv, nullptr);
    attn_fp16<<<dim3(16, 64), 256>>>();
    gemm_fp16<<<ggrid, 256>>>(3, bo, out);
}

// round 5
// speedup vs baseline: 3.5669x; 1.1698x over previous
#include <cuda_runtime.h>
#include <cuda_fp16.h>
#include <cstdint>
#include <math.h>

#define B_  8
#define S_  2048
#define D_  512
#define H_  8
#define DH_ 64
#define M_  (B_*S_)

// ---------------- scratch (allocation-free) ----------------
__device__ __half g_xhi[M_*D_], g_xlo[M_*D_];
__device__ __half g_whi[4*D_*D_], g_wlo[4*D_*D_];
__device__ __half g_qhi[M_*D_], g_qlo[M_*D_];   // [bh][s][64]
__device__ __half g_khi[M_*D_], g_klo[M_*D_];
__device__ __half g_vhi[M_*D_], g_vlo[M_*D_];
__device__ __half g_ohi[M_*D_], g_olo[M_*D_];   // [16384][512]

// ---------------- helpers ----------------
__device__ __forceinline__ uint32_t smem_u32(const void* p) {
    uint32_t a;
    asm("{ .reg .u64 t; cvta.to.shared.u64 t, %1; cvt.u32.u64 %0, t; }" : "=r"(a) : "l"(p));
    return a;
}
__device__ __forceinline__ void ldsm4(uint32_t* r, uint32_t a) {
    asm volatile("ldmatrix.sync.aligned.m8n8.x4.shared.b16 {%0,%1,%2,%3}, [%4];"
                 : "=r"(r[0]), "=r"(r[1]), "=r"(r[2]), "=r"(r[3]) : "r"(a));
}
__device__ __forceinline__ void ldsm4t(uint32_t* r, uint32_t a) {
    asm volatile("ldmatrix.sync.aligned.m8n8.x4.trans.shared.b16 {%0,%1,%2,%3}, [%4];"
                 : "=r"(r[0]), "=r"(r[1]), "=r"(r[2]), "=r"(r[3]) : "r"(a));
}
__device__ __forceinline__ void mma_f16(float* d, const uint32_t* a, uint32_t b0, uint32_t b1) {
    asm volatile(
        "mma.sync.aligned.m16n8k16.row.col.f32.f16.f16.f32 "
        "{%0,%1,%2,%3}, {%4,%5,%6,%7}, {%8,%9}, {%0,%1,%2,%3};"
        : "+f"(d[0]), "+f"(d[1]), "+f"(d[2]), "+f"(d[3])
        : "r"(a[0]), "r"(a[1]), "r"(a[2]), "r"(a[3]), "r"(b0), "r"(b1));
}
#define CPA16(dst_u32, src_ptr) \
    asm volatile("cp.async.cg.shared.global [%0], [%1], 16;" :: "r"(dst_u32), "l"(src_ptr))
#define CP_COMMIT() asm volatile("cp.async.commit_group;" ::: "memory")
#define CP_WAIT1()  asm volatile("cp.async.wait_group 1;" ::: "memory")
#define CP_WAIT0()  asm volatile("cp.async.wait_group 0;" ::: "memory")
#define MOD30(d) ((d) - (((d) * 2185) >> 16) * 30)   // exact for 0 <= d < 2048

// ---------------- split kernels ----------------
__global__ void split_x_kernel(const float* __restrict__ x) {
    int i = blockIdx.x * 256 + threadIdx.x;
    float v = x[i];
    __half h = __float2half_rn(v);
    g_xhi[i] = h;
    g_xlo[i] = __float2half_rn(v - __half2float(h));
}
__global__ void split_w_kernel(const float* __restrict__ Wq, const float* __restrict__ Wk,
                               const float* __restrict__ Wv, const float* __restrict__ Wo) {
    int z = blockIdx.y;
    const float* W = (z == 0) ? Wq : (z == 1) ? Wk : (z == 2) ? Wv : Wo;
    int i = blockIdx.x * 256 + threadIdx.x;
    float v = W[i];
    __half h = __float2half_rn(v);
    g_whi[z * D_ * D_ + i] = h;
    g_wlo[z * D_ * D_ + i] = __float2half_rn(v - __half2float(h));
}

// ---------------------------------------------------------------------------
// GEMM: C[16384,512] = A @ W + bias, split-fp16, cp.async double-buffered.
// K-chunk 64 (8 chunks). Stage layout (bytes, per stage of 71680):
//   A: [split 2][row 128][k 64 + pad 8]   = 36864
//   B: [split 2][k 64][n 128 + pad 8]     = 34816
// mode_in >= 0: that mode, col0 = bx*128. mode_in < 0: merged QKV,
//   mode = bx>>2, col0 = (bx&3)*128.
// ---------------------------------------------------------------------------
#define G_STAGE   71680
#define G_AROW    72
#define G_BROW    136
#define G_BOFF    36864

__global__ void __launch_bounds__(256) gemm_fp16(
    int mode_in, const float* __restrict__ bq, const float* __restrict__ bk,
    const float* __restrict__ bv, const float* __restrict__ bo, float* __restrict__ Cout)
{
    extern __shared__ char dynsmem[];

    const int bx = blockIdx.x;
    int mode, col0;
    if (mode_in < 0) { mode = bx >> 2; col0 = (bx & 3) * 128; }
    else             { mode = mode_in; col0 = bx * 128; }
    const float* bias = (mode == 0) ? bq : (mode == 1) ? bk : (mode == 2) ? bv : bo;

    const __half* Ahi = (mode == 3) ? g_ohi : g_xhi;
    const __half* Alo = (mode == 3) ? g_olo : g_xlo;
    const __half* Bhi = g_whi + (size_t)mode * D_ * D_;
    const __half* Blo = g_wlo + (size_t)mode * D_ * D_;

    const int tid = threadIdx.x, lane = tid & 31, wid = tid >> 5;
    const int wm = wid >> 1, wn = wid & 1;
    const int row0 = blockIdx.y * 128;

    float acc[2][8][4];
    #pragma unroll
    for (int mt = 0; mt < 2; mt++)
        #pragma unroll
        for (int nt = 0; nt < 8; nt++)
            #pragma unroll
            for (int e = 0; e < 4; e++) acc[mt][nt][e] = 0.f;

    auto load_chunk = [&](int c, int s) {
        char* st = dynsmem + s * G_STAGE;
        uint32_t stA = smem_u32(st);
        uint32_t stB = stA + G_BOFF;
        #pragma unroll
        for (int i = 0; i < 8; i++) {
            int u = tid + 256 * i;
            int spl = u >> 10, rr = (u >> 3) & 127, cc8 = (u & 7) * 8;
            const __half* src = (spl ? Alo : Ahi) + (size_t)(row0 + rr) * D_ + c * 64 + cc8;
            CPA16(stA + (spl * 128 + rr) * (G_AROW * 2) + cc8 * 2, src);
        }
        #pragma unroll
        for (int i = 0; i < 8; i++) {
            int u = tid + 256 * i;
            int spl = u >> 10, rr = (u >> 4) & 63, cc8 = (u & 15) * 8;
            const __half* src = (spl ? Blo : Bhi) + (size_t)(c * 64 + rr) * D_ + col0 + cc8;
            CPA16(stB + (spl * 64 + rr) * (G_BROW * 2) + cc8 * 2, src);
        }
        CP_COMMIT();
    };

    load_chunk(0, 0);

    for (int c = 0; c < 8; c++) {
        __syncthreads();                       // all warps done with buf[(c+1)&1]
        if (c < 7) { load_chunk(c + 1, (c + 1) & 1); CP_WAIT1(); }
        else       { CP_WAIT0(); }
        __syncthreads();                       // chunk c visible to all

        char* st = dynsmem + (c & 1) * G_STAGE;
        uint32_t stA = smem_u32(st);
        uint32_t stB = stA + G_BOFF;

        #pragma unroll
        for (int kt = 0; kt < 4; kt++) {
            uint32_t Ah[2][4], Al[2][4], Bh[8][2], Bl[8][2];
            #pragma unroll
            for (int mt = 0; mt < 2; mt++) {
                int rr = 32 * wm + 16 * mt + (lane & 15);
                int kk = 16 * kt + (lane >> 4) * 8;
                ldsm4(Ah[mt], stA + rr * (G_AROW * 2) + kk * 2);
                ldsm4(Al[mt], stA + (128 + rr) * (G_AROW * 2) + kk * 2);
            }
            #pragma unroll
            for (int ng = 0; ng < 4; ng++) {
                int kr = 16 * kt + (lane & 15);
                int cc = 64 * wn + 16 * ng + (lane >> 4) * 8;
                uint32_t t4[4];
                ldsm4t(t4, stB + kr * (G_BROW * 2) + cc * 2);
                Bh[2*ng][0] = t4[0]; Bh[2*ng][1] = t4[1];
                Bh[2*ng+1][0] = t4[2]; Bh[2*ng+1][1] = t4[3];
                ldsm4t(t4, stB + (64 + kr) * (G_BROW * 2) + cc * 2);
                Bl[2*ng][0] = t4[0]; Bl[2*ng][1] = t4[1];
                Bl[2*ng+1][0] = t4[2]; Bl[2*ng+1][1] = t4[3];
            }
            #pragma unroll
            for (int mt = 0; mt < 2; mt++)
                #pragma unroll
                for (int nt = 0; nt < 8; nt++) {
                    mma_f16(acc[mt][nt], Ah[mt], Bh[nt][0], Bh[nt][1]);
                    mma_f16(acc[mt][nt], Al[mt], Bh[nt][0], Bh[nt][1]);
                    mma_f16(acc[mt][nt], Ah[mt], Bl[nt][0], Bl[nt][1]);
                }
        }
    }

    // epilogue
    const float sc = (mode == 0) ? 0.125f : 1.f;
    __half* Dhi = (mode == 0) ? g_qhi : (mode == 1) ? g_khi : g_vhi;
    __half* Dlo = (mode == 0) ? g_qlo : (mode == 1) ? g_klo : g_vlo;
    #pragma unroll
    for (int mt = 0; mt < 2; mt++)
        #pragma unroll
        for (int nt = 0; nt < 8; nt++) {
            int row = row0 + 32 * wm + 16 * mt + (lane >> 2);
            int col = col0 + 64 * wn + 8 * nt + 2 * (lane & 3);
            float b0 = bias[col], b1 = bias[col + 1];
            float c0 = acc[mt][nt][0] + b0, c1 = acc[mt][nt][1] + b1;
            float c2 = acc[mt][nt][2] + b0, c3 = acc[mt][nt][3] + b1;
            if (mode == 3) {
                *(float2*)&Cout[(size_t)row * D_ + col] = make_float2(c0, c1);
                *(float2*)&Cout[(size_t)(row + 8) * D_ + col] = make_float2(c2, c3);
            } else {
                c0 *= sc; c1 *= sc; c2 *= sc; c3 *= sc;
                int h = col >> 6, dh = col & 63;
                int b = row >> 11, s = row & 2047;
                size_t i0 = ((size_t)(b * H_ + h) * S_ + s) * DH_ + dh;
                half2 h01 = __floats2half2_rn(c0, c1);
                *(half2*)&Dhi[i0] = h01;
                *(half2*)&Dlo[i0] = __floats2half2_rn(c0 - __low2float(h01), c1 - __high2float(h01));
                half2 h23 = __floats2half2_rn(c2, c3);
                *(half2*)&Dhi[i0 + 8 * DH_] = h23;
                *(half2*)&Dlo[i0 + 8 * DH_] = __floats2half2_rn(c2 - __low2float(h23), c3 - __high2float(h23));
            }
        }
}

// ---------------------------------------------------------------------------
// Flash attention, split-fp16 mma.sync, cp.async double-buffered K/V tiles.
// Stage layout (36864B per stage): [Khi][Klo][Vhi][Vlo], each 64 x (64+8) halves.
// Q staged through stage 0 before the pipeline starts.
// grid = (16, 64), 256 threads.
// ---------------------------------------------------------------------------
#define A_STAGE  36864
#define A_ARR    9216
#define A_ROW    144      // bytes per row (72 halves)

__global__ void __launch_bounds__(256) attn_fp16()
{
    extern __shared__ char dynsmem[];
    __shared__ float btab[32];

    const int bh = blockIdx.y, tid = threadIdx.x, lane = tid & 31, w = tid >> 5;
    const int q0 = blockIdx.x * 128;
    if (tid < 30) btab[tid] = log1pf(2.f + __expf(-2.f * (float)(tid * tid)));

    const size_t base = (size_t)bh * S_ * DH_;
    const uint32_t st0 = smem_u32(dynsmem);

    // ---- stage Q into stage 0: arr = spl*2 + (rr>=64), row rr&63 ----
    #pragma unroll
    for (int i = 0; i < 8; i++) {
        int u = tid + 256 * i;                // 0..2047 float4 units
        int spl = u >> 10, rr = (u >> 3) & 127, cc8 = (u & 7) * 8;
        const __half* src = (spl ? g_qlo : g_qhi) + base + (size_t)(q0 + rr) * DH_ + cc8;
        float4 v = *(const float4*)src;
        int arr = spl * 2 + (rr >> 6);
        *(float4*)(dynsmem + arr * A_ARR + (rr & 63) * A_ROW + cc8 * 2) = v;
    }
    __syncthreads();

    uint32_t Qh[4][4], Ql[4][4];
    {
        int hiArr = (w >= 4) ? 1 : 0;
        int srow = (16 * w) & 63;
        #pragma unroll
        for (int kt = 0; kt < 4; kt++) {
            int r = srow + (lane & 15), k = 16 * kt + (lane >> 4) * 8;
            ldsm4(Qh[kt], st0 + hiArr * A_ARR + r * A_ROW + k * 2);
            ldsm4(Ql[kt], st0 + (2 + hiArr) * A_ARR + r * A_ROW + k * 2);
        }
    }
    __syncthreads();    // everyone has Q frags; stage 0 reusable

    auto load_tile = [&](int j, int s) {
        uint32_t st = st0 + s * A_STAGE;
        #pragma unroll
        for (int i = 0; i < 8; i++) {
            int u = tid + 256 * i;            // 4 arrays x 512 units
            int arr = u >> 9, rr = (u >> 3) & 63, cc8 = (u & 7) * 8;
            const __half* src =
                (arr == 0 ? g_khi : arr == 1 ? g_klo : arr == 2 ? g_vhi : g_vlo)
                + base + (size_t)(j * 64 + rr) * DH_ + cc8;
            CPA16(st + arr * A_ARR + rr * A_ROW + cc8 * 2, src);
        }
        CP_COMMIT();
    };

    load_tile(0, 0);

    float O[8][4];
    #pragma unroll
    for (int nt = 0; nt < 8; nt++)
        #pragma unroll
        for (int e = 0; e < 4; e++) O[nt][e] = 0.f;
    float m0 = -1e30f, m1 = -1e30f, l0 = 0.f, l1 = 0.f;
    const int row_a = q0 + 16 * w + (lane >> 2);

    for (int j = 0; j < 32; j++) {
        __syncthreads();
        if (j < 31) { load_tile(j + 1, (j + 1) & 1); CP_WAIT1(); }
        else        { CP_WAIT0(); }
        __syncthreads();

        const uint32_t st = st0 + (j & 1) * A_STAGE;
        const int j0 = j * 64;

        // ---- S = Q K^T (3-term split) ----
        float Sc[8][4];
        #pragma unroll
        for (int nt = 0; nt < 8; nt++)
            #pragma unroll
            for (int e = 0; e < 4; e++) Sc[nt][e] = 0.f;

        #pragma unroll
        for (int kt = 0; kt < 4; kt++) {
            uint32_t Kh[8][2], Kl[8][2];
            #pragma unroll
            for (int kq = 0; kq < 4; kq++) {
                int kr = 16 * kq + (lane & 15), kk = 16 * kt + (lane >> 4) * 8;
                uint32_t t4[4];
                ldsm4(t4, st + 0 * A_ARR + kr * A_ROW + kk * 2);
                Kh[2*kq][0] = t4[0]; Kh[2*kq][1] = t4[2];
                Kh[2*kq+1][0] = t4[1]; Kh[2*kq+1][1] = t4[3];
                ldsm4(t4, st + 1 * A_ARR + kr * A_ROW + kk * 2);
                Kl[2*kq][0] = t4[0]; Kl[2*kq][1] = t4[2];
                Kl[2*kq+1][0] = t4[1]; Kl[2*kq+1][1] = t4[3];
            }
            #pragma unroll
            for (int nt = 0; nt < 8; nt++) {
                mma_f16(Sc[nt], Qh[kt], Kh[nt][0], Kh[nt][1]);
                mma_f16(Sc[nt], Ql[kt], Kh[nt][0], Kh[nt][1]);
                mma_f16(Sc[nt], Qh[kt], Kl[nt][0], Kl[nt][1]);
            }
        }

        // ---- bias + online softmax ----
        #pragma unroll
        for (int nt = 0; nt < 8; nt++) {
            int colb = j0 + 8 * nt + 2 * (lane & 3);
            #pragma unroll
            for (int e = 0; e < 2; e++) {
                int da = row_a - (colb + e); da = da < 0 ? -da : da;
                int db = row_a + 8 - (colb + e); db = db < 0 ? -db : db;
                Sc[nt][e]     += btab[MOD30(da)];
                Sc[nt][2 + e] += btab[MOD30(db)];
            }
        }
        float ma = m0, mb = m1;
        #pragma unroll
        for (int nt = 0; nt < 8; nt++) {
            ma = fmaxf(ma, fmaxf(Sc[nt][0], Sc[nt][1]));
            mb = fmaxf(mb, fmaxf(Sc[nt][2], Sc[nt][3]));
        }
        ma = fmaxf(ma, __shfl_xor_sync(0xFFFFFFFF, ma, 1));
        ma = fmaxf(ma, __shfl_xor_sync(0xFFFFFFFF, ma, 2));
        mb = fmaxf(mb, __shfl_xor_sync(0xFFFFFFFF, mb, 1));
        mb = fmaxf(mb, __shfl_xor_sync(0xFFFFFFFF, mb, 2));
        float aa = __expf(m0 - ma), ab = __expf(m1 - mb);
        m0 = ma; m1 = mb;
        float suma = 0.f, sumb = 0.f;
        #pragma unroll
        for (int nt = 0; nt < 8; nt++) {
            Sc[nt][0] = __expf(Sc[nt][0] - ma); suma += Sc[nt][0];
            Sc[nt][1] = __expf(Sc[nt][1] - ma); suma += Sc[nt][1];
            Sc[nt][2] = __expf(Sc[nt][2] - mb); sumb += Sc[nt][2];
            Sc[nt][3] = __expf(Sc[nt][3] - mb); sumb += Sc[nt][3];
        }
        suma += __shfl_xor_sync(0xFFFFFFFF, suma, 1);
        suma += __shfl_xor_sync(0xFFFFFFFF, suma, 2);
        sumb += __shfl_xor_sync(0xFFFFFFFF, sumb, 1);
        sumb += __shfl_xor_sync(0xFFFFFFFF, sumb, 2);
        l0 = l0 * aa + suma;
        l1 = l1 * ab + sumb;
        #pragma unroll
        for (int nt = 0; nt < 8; nt++) {
            O[nt][0] *= aa; O[nt][1] *= aa; O[nt][2] *= ab; O[nt][3] *= ab;
        }

        // ---- O += P V (3-term split) ----
        #pragma unroll
        for (int kg = 0; kg < 4; kg++) {
            uint32_t Ph[4], Pl[4];
            #pragma unroll
            for (int hx = 0; hx < 2; hx++) {
                int nt = 2 * kg + hx;
                half2 ha = __floats2half2_rn(Sc[nt][0], Sc[nt][1]);
                half2 hb = __floats2half2_rn(Sc[nt][2], Sc[nt][3]);
                Ph[2 * hx]     = *(uint32_t*)&ha;
                Ph[2 * hx + 1] = *(uint32_t*)&hb;
                half2 la = __floats2half2_rn(Sc[nt][0] - __low2float(ha),
                                             Sc[nt][1] - __high2float(ha));
                half2 lb = __floats2half2_rn(Sc[nt][2] - __low2float(hb),
                                             Sc[nt][3] - __high2float(hb));
                Pl[2 * hx]     = *(uint32_t*)&la;
                Pl[2 * hx + 1] = *(uint32_t*)&lb;
            }
            #pragma unroll
            for (int vg = 0; vg < 4; vg++) {
                int kr = 16 * kg + (lane & 15), dd = 16 * vg + (lane >> 4) * 8;
                uint32_t t4[4], u4[4];
                ldsm4t(t4, st + 2 * A_ARR + kr * A_ROW + dd * 2);
                ldsm4t(u4, st + 3 * A_ARR + kr * A_ROW + dd * 2);
                mma_f16(O[2*vg],   Ph, t4[0], t4[1]);
                mma_f16(O[2*vg],   Pl, t4[0], t4[1]);
                mma_f16(O[2*vg],   Ph, u4[0], u4[1]);
                mma_f16(O[2*vg+1], Ph, t4[2], t4[3]);
                mma_f16(O[2*vg+1], Pl, t4[2], t4[3]);
                mma_f16(O[2*vg+1], Ph, u4[2], u4[3]);
            }
        }
    }

    // ---- epilogue: normalize, split, store ----
    const float inva = 1.f / l0, invb = 1.f / l1;
    const int b = bh >> 3, h = bh & 7;
    #pragma unroll
    for (int nt = 0; nt < 8; nt++) {
        int dh = 8 * nt + 2 * (lane & 3);
        float c0 = O[nt][0] * inva, c1 = O[nt][1] * inva;
        float c2 = O[nt][2] * invb, c3 = O[nt][3] * invb;
        size_t ra = ((size_t)(b * S_ + row_a)) * D_ + h * DH_ + dh;
        size_t rb = ra + 8 * D_;
        half2 h01 = __floats2half2_rn(c0, c1);
        *(half2*)&g_ohi[ra] = h01;
        *(half2*)&g_olo[ra] = __floats2half2_rn(c0 - __low2float(h01), c1 - __high2float(h01));
        half2 h23 = __floats2half2_rn(c2, c3);
        *(half2*)&g_ohi[rb] = h23;
        *(half2*)&g_olo[rb] = __floats2half2_rn(c2 - __low2float(h23), c3 - __high2float(h23));
    }
}

// ---------------------------------------------------------------------------
extern "C" void kernel_launch(void* const* d_in, const int* in_sizes, int n_in,
                              void* d_out, int out_size)
{
    const float* x  = (const float*)d_in[0];
    const float* Wq = (const float*)d_in[1];
    const float* bq = (const float*)d_in[2];
    const float* Wk = (const float*)d_in[3];
    const float* bk = (const float*)d_in[4];
    const float* Wv = (const float*)d_in[5];
    const float* bv = (const float*)d_in[6];
    const float* Wo = (const float*)d_in[7];
    const float* bo = (const float*)d_in[8];
    float* out = (float*)d_out;

    // Idempotent, not a stream op — safe to call every time (incl. during capture).
    cudaFuncSetAttribute(gemm_fp16, cudaFuncAttributeMaxDynamicSharedMemorySize, 2 * G_STAGE);
    cudaFuncSetAttribute(attn_fp16, cudaFuncAttributeMaxDynamicSharedMemorySize, 2 * A_STAGE);

    split_x_kernel<<<M_ * D_ / 256, 256>>>(x);
    split_w_kernel<<<dim3(D_ * D_ / 256, 4), 256>>>(Wq, Wk, Wv, Wo);

    gemm_fp16<<<dim3(12, 128), 256, 2 * G_STAGE>>>(-1, bq, bk, bv, bo, nullptr);  // Q,K,V merged
    attn_fp16<<<dim3(16, 64), 256, 2 * A_STAGE>>>();
    gemm_fp16<<<dim3(4, 128), 256, 2 * G_STAGE>>>(3, bq, bk, bv, bo, out);
}